// round 12
// baseline (speedup 1.0000x reference)
#include <cuda_runtime.h>
#include <math.h>

#define N_NODES  50000
#define N_EDGES  800000
#define N_GRAPHS 256
#define FEAT     128
#define STATE    64
#define ROUNDS   4
#define M_OUT    32

#define TILE_ROWS 64
#define APITCH    68          // padded smem pitch (floats) -> no bank conflicts
#define ROW_BLOCKS ((N_NODES + TILE_ROWS - 1) / TILE_ROWS)   // 782

// Scratch (allocation-free rule: __device__ globals)
__device__ float g_state[N_NODES * STATE];        // 12.8 MB
__device__ float g_msgbuf[2][N_NODES * STATE];    // 2x 12.8 MB (ping-pong: fixes
                                                  // cross-block race in fused kernel)
__device__ float g_graph[N_GRAPHS * STATE];       // 64 KB
// CSR-by-dst scratch (built once per launch, reused all 4 rounds)
__device__ int   g_cnt[N_NODES];
__device__ int   g_rowptr[N_NODES + 1];
__device__ int   g_cursor[N_NODES];
__device__ int   g_esrc[N_EDGES];

// ---------------------------------------------------------------------------
__global__ void k_zero() {
    int t = blockIdx.x * blockDim.x + threadIdx.x;
    if (t < N_NODES) g_cnt[t] = 0;
    if (t < N_GRAPHS * STATE) g_graph[t] = 0.0f;
}

// ---------------------------------------------------------------------------
// CSR build: histogram of dst, scan, scatter of src ids
// ---------------------------------------------------------------------------
__global__ void k_hist(const int* __restrict__ ei) {
    int t = blockIdx.x * blockDim.x + threadIdx.x;
    if (t < N_EDGES) atomicAdd(&g_cnt[__ldg(&ei[N_EDGES + t])], 1);
}

__global__ __launch_bounds__(1024) void k_scan() {
    __shared__ int ps[1024];
    const int CH = (N_NODES + 1023) / 1024;   // 49
    int t = threadIdx.x;
    int base = t * CH;

    int sum = 0;
    for (int i = 0; i < CH; i++) {
        int idx = base + i;
        if (idx < N_NODES) sum += g_cnt[idx];
    }
    ps[t] = sum;
    __syncthreads();
    for (int off = 1; off < 1024; off <<= 1) {
        int v = (t >= off) ? ps[t - off] : 0;
        __syncthreads();
        ps[t] += v;
        __syncthreads();
    }
    int run = (t == 0) ? 0 : ps[t - 1];
    for (int i = 0; i < CH; i++) {
        int idx = base + i;
        if (idx < N_NODES) {
            int c = g_cnt[idx];
            g_rowptr[idx] = run;
            g_cursor[idx] = run;
            run += c;
        }
    }
    if (t == 1023) g_rowptr[N_NODES] = run;   // = N_EDGES
}

__global__ void k_scatter(const int* __restrict__ ei) {
    int t = blockIdx.x * blockDim.x + threadIdx.x;
    if (t >= N_EDGES) return;
    int d = __ldg(&ei[N_EDGES + t]);
    int pos = atomicAdd(&g_cursor[d], 1);
    g_esrc[pos] = __ldg(&ei[t]);
}

// ===========================================================================
// Register-tiled GEMM helpers.
// ===========================================================================
__device__ __forceinline__ void load_tileA(float* sA, const float* __restrict__ src,
                                           int blkRow, int rowStride, int colOff, int tid) {
#pragma unroll
    for (int p = 0; p < 4; p++) {
        int idx = p * 1024 + tid * 4;
        int row = idx >> 6, col = idx & 63;
        float4 v = make_float4(0.f, 0.f, 0.f, 0.f);
        int gr = blkRow + row;
        if (gr < N_NODES)
            v = *reinterpret_cast<const float4*>(&src[gr * rowStride + colOff + col]);
        *reinterpret_cast<float4*>(&sA[row * APITCH + col]) = v;
    }
}

__device__ __forceinline__ void load_tileW(float* sW, const float* __restrict__ W, int tid) {
#pragma unroll
    for (int p = 0; p < 4; p++) {
        int idx = p * 1024 + tid * 4;
        *reinterpret_cast<float4*>(&sW[idx]) =
            *reinterpret_cast<const float4*>(&W[idx]);
    }
}

__device__ __forceinline__ void mm_tile(float acc[4][4], const float* sA, const float* sW,
                                        int r0, int c0) {
#pragma unroll 8
    for (int k = 0; k < 64; k++) {
        float4 w = *reinterpret_cast<const float4*>(&sW[k * 64 + c0]);
        float a[4];
#pragma unroll
        for (int i = 0; i < 4; i++) a[i] = sA[(r0 + i) * APITCH + k];
#pragma unroll
        for (int i = 0; i < 4; i++) {
            acc[i][0] = fmaf(a[i], w.x, acc[i][0]);
            acc[i][1] = fmaf(a[i], w.y, acc[i][1]);
            acc[i][2] = fmaf(a[i], w.z, acc[i][2]);
            acc[i][3] = fmaf(a[i], w.w, acc[i][3]);
        }
    }
}

// ---------------------------------------------------------------------------
// k_input: state = relu(x @ in_W + in_b); msgbuf[0] = relu(state @ msg_W[0] + b0)
// ---------------------------------------------------------------------------
__global__ __launch_bounds__(256) void k_input(const float* __restrict__ x,
                       const float* __restrict__ W,  const float* __restrict__ b,
                       const float* __restrict__ mW, const float* __restrict__ mb) {
    __shared__ float sA[TILE_ROWS * APITCH];
    __shared__ float sW[64 * 64];

    int tid = threadIdx.x;
    int ty = tid >> 4, tx = tid & 15;
    int r0 = ty * 4, c0 = tx * 4;
    int blkRow = blockIdx.x * TILE_ROWS;

    float acc[4][4];
#pragma unroll
    for (int i = 0; i < 4; i++)
#pragma unroll
        for (int j = 0; j < 4; j++) acc[i][j] = 0.0f;

#pragma unroll
    for (int chunk = 0; chunk < 2; chunk++) {
        load_tileA(sA, x, blkRow, FEAT, chunk * 64, tid);
        load_tileW(sW, W + chunk * 64 * STATE, tid);
        __syncthreads();
        mm_tile(acc, sA, sW, r0, c0);
        __syncthreads();
    }

    float4 bias = *reinterpret_cast<const float4*>(&b[c0]);
    float st[4][4];
#pragma unroll
    for (int i = 0; i < 4; i++) {
        st[i][0] = fmaxf(acc[i][0] + bias.x, 0.0f);
        st[i][1] = fmaxf(acc[i][1] + bias.y, 0.0f);
        st[i][2] = fmaxf(acc[i][2] + bias.z, 0.0f);
        st[i][3] = fmaxf(acc[i][3] + bias.w, 0.0f);
        int gr = blkRow + r0 + i;
        if (gr < N_NODES)
            *reinterpret_cast<float4*>(&g_state[gr * STATE + c0]) =
                make_float4(st[i][0], st[i][1], st[i][2], st[i][3]);
    }

    // msg[0] from the state tile (reuse smem)
#pragma unroll
    for (int i = 0; i < 4; i++)
        *reinterpret_cast<float4*>(&sA[(r0 + i) * APITCH + c0]) =
            make_float4(st[i][0], st[i][1], st[i][2], st[i][3]);
    load_tileW(sW, mW, tid);
    __syncthreads();

#pragma unroll
    for (int i = 0; i < 4; i++)
#pragma unroll
        for (int j = 0; j < 4; j++) acc[i][j] = 0.0f;
    mm_tile(acc, sA, sW, r0, c0);

    float4 mbias = *reinterpret_cast<const float4*>(&mb[c0]);
#pragma unroll
    for (int i = 0; i < 4; i++) {
        int gr = blkRow + r0 + i;
        if (gr < N_NODES)
            *reinterpret_cast<float4*>(&g_msgbuf[0][gr * STATE + c0]) =
                make_float4(fmaxf(acc[i][0] + mbias.x, 0.0f),
                            fmaxf(acc[i][1] + mbias.y, 0.0f),
                            fmaxf(acc[i][2] + mbias.z, 0.0f),
                            fmaxf(acc[i][3] + mbias.w, 0.0f));
    }
}

// ---------------------------------------------------------------------------
// FUSED gather + update (race-free via msg ping-pong):
//   agg_tile = CSR-gather of msgIn        (straight into smem)
//   state  += relu(agg_tile @ upd_W + b)
//   if HAS_MSG: msgOut = relu(state @ msg_W[r+1] + mb)   (msgOut != msgIn)
// ---------------------------------------------------------------------------
template <int HAS_MSG>
__global__ __launch_bounds__(256) void k_gupd(const float* __restrict__ msgIn,
                      float* __restrict__ msgOut,
                      const float* __restrict__ W,  const float* __restrict__ b,
                      const float* __restrict__ mW, const float* __restrict__ mb) {
    __shared__ float sA[TILE_ROWS * APITCH];
    __shared__ float sW[64 * 64];

    int tid = threadIdx.x;
    int grp = tid >> 4;            // 0..15 (node within sub-tile)
    int c4  = (tid & 15) << 2;     // float4 chunk offset
    int blkRow = blockIdx.x * TILE_ROWS;

    load_tileW(sW, W, tid);        // independent; overlaps with gather below

#pragma unroll
    for (int sub = 0; sub < 4; sub++) {
        int lrow = sub * 16 + grp;
        int node = blkRow + lrow;
        float4 acc = make_float4(0.f, 0.f, 0.f, 0.f);
        if (node < N_NODES) {
            int e   = __ldg(&g_rowptr[node]);
            int end = __ldg(&g_rowptr[node + 1]);
            for (; e + 3 < end; e += 4) {
                int s0 = __ldg(&g_esrc[e]);
                int s1 = __ldg(&g_esrc[e + 1]);
                int s2 = __ldg(&g_esrc[e + 2]);
                int s3 = __ldg(&g_esrc[e + 3]);
                float4 v0 = *reinterpret_cast<const float4*>(&msgIn[s0 * STATE + c4]);
                float4 v1 = *reinterpret_cast<const float4*>(&msgIn[s1 * STATE + c4]);
                float4 v2 = *reinterpret_cast<const float4*>(&msgIn[s2 * STATE + c4]);
                float4 v3 = *reinterpret_cast<const float4*>(&msgIn[s3 * STATE + c4]);
                acc.x += (v0.x + v1.x) + (v2.x + v3.x);
                acc.y += (v0.y + v1.y) + (v2.y + v3.y);
                acc.z += (v0.z + v1.z) + (v2.z + v3.z);
                acc.w += (v0.w + v1.w) + (v2.w + v3.w);
            }
            for (; e < end; e++) {
                int s0 = __ldg(&g_esrc[e]);
                float4 v0 = *reinterpret_cast<const float4*>(&msgIn[s0 * STATE + c4]);
                acc.x += v0.x; acc.y += v0.y; acc.z += v0.z; acc.w += v0.w;
            }
        }
        *reinterpret_cast<float4*>(&sA[lrow * APITCH + c4]) = acc;
    }
    __syncthreads();

    int ty = tid >> 4, tx = tid & 15;
    int r0 = ty * 4, c0 = tx * 4;

    float acc[4][4];
#pragma unroll
    for (int i = 0; i < 4; i++)
#pragma unroll
        for (int j = 0; j < 4; j++) acc[i][j] = 0.0f;
    mm_tile(acc, sA, sW, r0, c0);

    float4 bias = *reinterpret_cast<const float4*>(&b[c0]);
    float st[4][4];
#pragma unroll
    for (int i = 0; i < 4; i++) {
        int gr = blkRow + r0 + i;
        if (gr < N_NODES) {
            float4 old = *reinterpret_cast<const float4*>(&g_state[gr * STATE + c0]);
            st[i][0] = old.x + fmaxf(acc[i][0] + bias.x, 0.0f);
            st[i][1] = old.y + fmaxf(acc[i][1] + bias.y, 0.0f);
            st[i][2] = old.z + fmaxf(acc[i][2] + bias.z, 0.0f);
            st[i][3] = old.w + fmaxf(acc[i][3] + bias.w, 0.0f);
            *reinterpret_cast<float4*>(&g_state[gr * STATE + c0]) =
                make_float4(st[i][0], st[i][1], st[i][2], st[i][3]);
        } else {
            st[i][0] = st[i][1] = st[i][2] = st[i][3] = 0.0f;
        }
    }

    if (HAS_MSG) {
        __syncthreads();
#pragma unroll
        for (int i = 0; i < 4; i++)
            *reinterpret_cast<float4*>(&sA[(r0 + i) * APITCH + c0]) =
                make_float4(st[i][0], st[i][1], st[i][2], st[i][3]);
        load_tileW(sW, mW, tid);
        __syncthreads();

#pragma unroll
        for (int i = 0; i < 4; i++)
#pragma unroll
            for (int j = 0; j < 4; j++) acc[i][j] = 0.0f;
        mm_tile(acc, sA, sW, r0, c0);

        float4 mbias = *reinterpret_cast<const float4*>(&mb[c0]);
#pragma unroll
        for (int i = 0; i < 4; i++) {
            int gr = blkRow + r0 + i;
            if (gr < N_NODES)
                *reinterpret_cast<float4*>(&msgOut[gr * STATE + c0]) =
                    make_float4(fmaxf(acc[i][0] + mbias.x, 0.0f),
                                fmaxf(acc[i][1] + mbias.y, 0.0f),
                                fmaxf(acc[i][2] + mbias.z, 0.0f),
                                fmaxf(acc[i][3] + mbias.w, 0.0f));
        }
    }
}

// ---------------------------------------------------------------------------
// graph_state = segment_sum(state, batch)  -> [256, 64]
// ---------------------------------------------------------------------------
__global__ void k_pool(const int* __restrict__ batch) {
    int t = blockIdx.x * blockDim.x + threadIdx.x;
    int row = t >> 4;
    if (row >= N_NODES) return;
    int c = (t & 15) << 2;
    int g = __ldg(&batch[row]);

    const float4 v = *reinterpret_cast<const float4*>(&g_state[row * STATE + c]);
    float* a = &g_graph[g * STATE + c];
    asm volatile("red.global.add.v4.f32 [%0], {%1,%2,%3,%4};"
                 :: "l"(a), "f"(v.x), "f"(v.y), "f"(v.z), "f"(v.w)
                 : "memory");
}

// ---------------------------------------------------------------------------
// mean = gs @ mean_W + mean_b ; std = exp(0.5*clip(gs @ lv_W + lv_b, -20, 2))
// ---------------------------------------------------------------------------
__global__ void k_head(const float* __restrict__ meanW, const float* __restrict__ meanB,
                       const float* __restrict__ lvW,   const float* __restrict__ lvB,
                       float* __restrict__ out) {
    __shared__ float s[STATE];
    int g = blockIdx.x;
    int m = threadIdx.x;
    s[m]      = g_graph[g * STATE + m];
    s[m + 32] = g_graph[g * STATE + m + 32];
    __syncthreads();

    float accM = meanB[m];
    float accL = lvB[m];
#pragma unroll
    for (int k = 0; k < STATE; k++) {
        float sv = s[k];
        accM = fmaf(sv, meanW[k * M_OUT + m], accM);
        accL = fmaf(sv, lvW[k * M_OUT + m], accL);
    }
    out[g * M_OUT + m] = accM;
    float lv = fminf(fmaxf(accL, -20.0f), 2.0f);
    out[N_GRAPHS * M_OUT + g * M_OUT + m] = expf(0.5f * lv);
}

// ---------------------------------------------------------------------------
extern "C" void kernel_launch(void* const* d_in, const int* in_sizes, int n_in,
                              void* d_out, int out_size) {
    const float* x     = (const float*)d_in[0];
    const int*   ei    = (const int*)d_in[1];
    const int*   batch = (const int*)d_in[2];
    const float* in_W  = (const float*)d_in[3];
    const float* in_b  = (const float*)d_in[4];
    const float* msg_W = (const float*)d_in[5];    // [4,64,64]
    const float* msg_b = (const float*)d_in[6];    // [4,64]
    const float* upd_W = (const float*)d_in[7];
    const float* upd_b = (const float*)d_in[8];
    const float* meanW = (const float*)d_in[9];
    const float* meanB = (const float*)d_in[10];
    const float* lvW   = (const float*)d_in[11];
    const float* lvB   = (const float*)d_in[12];
    float* out = (float*)d_out;

    const int zeroBlocks = (N_NODES + 255) / 256;
    const int edgeBlocks = (N_EDGES + 255) / 256;
    const int poolBlocks = (N_NODES * 16 + 255) / 256;

    // Resolve device-global msg buffers to raw pointers (host-side, once per call)
    float* msgA;  // = g_msgbuf[0]
    float* msgB;  // = g_msgbuf[1]
    {
        void* p;
        cudaGetSymbolAddress(&p, g_msgbuf);
        msgA = (float*)p;
        msgB = msgA + N_NODES * STATE;
    }

    // CSR build (once per launch; reused by all 4 rounds)
    k_zero<<<zeroBlocks, 256>>>();
    k_hist<<<edgeBlocks, 256>>>(ei);
    k_scan<<<1, 1024>>>();
    k_scatter<<<edgeBlocks, 256>>>(ei);

    k_input<<<ROW_BLOCKS, 256>>>(x, in_W, in_b, msg_W, msg_b);  // state + msgbuf[0]

    for (int r = 0; r < ROUNDS; r++) {
        const float* uW = upd_W + r * STATE * STATE;
        const float* ub = upd_b + r * STATE;
        const float* mIn  = (r & 1) ? msgB : msgA;
        float*       mOut = (r & 1) ? msgA : msgB;
        if (r < ROUNDS - 1) {
            k_gupd<1><<<ROW_BLOCKS, 256>>>(mIn, mOut, uW, ub,
                                           msg_W + (r + 1) * STATE * STATE,
                                           msg_b + (r + 1) * STATE);
        } else {
            k_gupd<0><<<ROW_BLOCKS, 256>>>(mIn, nullptr, uW, ub, nullptr, nullptr);
        }
    }

    k_pool<<<poolBlocks, 256>>>(batch);
    k_head<<<N_GRAPHS, M_OUT>>>(meanW, meanB, lvW, lvB, out);
}

// round 13
// speedup vs baseline: 1.0469x; 1.0469x over previous
#include <cuda_runtime.h>
#include <cuda_fp16.h>
#include <math.h>

#define N_NODES  50000
#define N_EDGES  800000
#define N_GRAPHS 256
#define FEAT     128
#define STATE    64
#define ROUNDS   4
#define M_OUT    32

#define TILE_ROWS 64
#define APITCH    68          // padded smem pitch (floats) -> no bank conflicts
#define ROW_BLOCKS ((N_NODES + TILE_ROWS - 1) / TILE_ROWS)   // 782

// Scratch (allocation-free rule: __device__ globals)
__device__ float  g_state[N_NODES * STATE];   // 12.8 MB
__device__ __half g_msg[N_NODES * STATE];     // 6.4 MB (fp16 message buffer)
__device__ float  g_agg[N_NODES * STATE];     // 12.8 MB
__device__ float  g_graph[N_GRAPHS * STATE];  // 64 KB
// CSR-by-dst scratch (built once per launch, reused all 4 rounds)
__device__ int    g_cnt[N_NODES];
__device__ int    g_rowptr[N_NODES + 1];
__device__ int    g_cursor[N_NODES];
__device__ int    g_esrc[N_EDGES];

// ---------------------------------------------------------------------------
__global__ void k_zero() {
    int t = blockIdx.x * blockDim.x + threadIdx.x;
    if (t < N_NODES) g_cnt[t] = 0;
    if (t < N_GRAPHS * STATE) g_graph[t] = 0.0f;
}

// ---------------------------------------------------------------------------
// CSR build: histogram of dst, scan, scatter of src ids
// ---------------------------------------------------------------------------
__global__ void k_hist(const int* __restrict__ ei) {
    int t = blockIdx.x * blockDim.x + threadIdx.x;
    if (t < N_EDGES) atomicAdd(&g_cnt[__ldg(&ei[N_EDGES + t])], 1);
}

__global__ __launch_bounds__(1024) void k_scan() {
    __shared__ int ps[1024];
    const int CH = (N_NODES + 1023) / 1024;   // 49
    int t = threadIdx.x;
    int base = t * CH;

    int sum = 0;
    for (int i = 0; i < CH; i++) {
        int idx = base + i;
        if (idx < N_NODES) sum += g_cnt[idx];
    }
    ps[t] = sum;
    __syncthreads();
    for (int off = 1; off < 1024; off <<= 1) {
        int v = (t >= off) ? ps[t - off] : 0;
        __syncthreads();
        ps[t] += v;
        __syncthreads();
    }
    int run = (t == 0) ? 0 : ps[t - 1];
    for (int i = 0; i < CH; i++) {
        int idx = base + i;
        if (idx < N_NODES) {
            int c = g_cnt[idx];
            g_rowptr[idx] = run;
            g_cursor[idx] = run;
            run += c;
        }
    }
    if (t == 1023) g_rowptr[N_NODES] = run;   // = N_EDGES
}

__global__ void k_scatter(const int* __restrict__ ei) {
    int t = blockIdx.x * blockDim.x + threadIdx.x;
    if (t >= N_EDGES) return;
    int d = __ldg(&ei[N_EDGES + t]);
    int pos = atomicAdd(&g_cursor[d], 1);
    g_esrc[pos] = __ldg(&ei[t]);
}

// ===========================================================================
// fp16 helpers
// ===========================================================================
__device__ __forceinline__ float4 ld_msg4(const __half* p) {   // 4 halves (8B)
    uint2 u = *reinterpret_cast<const uint2*>(p);
    float2 f0 = __half22float2(*reinterpret_cast<__half2*>(&u.x));
    float2 f1 = __half22float2(*reinterpret_cast<__half2*>(&u.y));
    return make_float4(f0.x, f0.y, f1.x, f1.y);
}

__device__ __forceinline__ void st_msg4(__half* p, float a, float b, float c, float d) {
    uint2 u;
    *reinterpret_cast<__half2*>(&u.x) = __floats2half2_rn(a, b);
    *reinterpret_cast<__half2*>(&u.y) = __floats2half2_rn(c, d);
    *reinterpret_cast<uint2*>(p) = u;
}

// ===========================================================================
// Register-tiled GEMM helpers.
// ===========================================================================
__device__ __forceinline__ void load_tileA(float* sA, const float* __restrict__ src,
                                           int blkRow, int rowStride, int colOff, int tid) {
#pragma unroll
    for (int p = 0; p < 4; p++) {
        int idx = p * 1024 + tid * 4;
        int row = idx >> 6, col = idx & 63;
        float4 v = make_float4(0.f, 0.f, 0.f, 0.f);
        int gr = blkRow + row;
        if (gr < N_NODES)
            v = *reinterpret_cast<const float4*>(&src[gr * rowStride + colOff + col]);
        *reinterpret_cast<float4*>(&sA[row * APITCH + col]) = v;
    }
}

__device__ __forceinline__ void load_tileW(float* sW, const float* __restrict__ W, int tid) {
#pragma unroll
    for (int p = 0; p < 4; p++) {
        int idx = p * 1024 + tid * 4;
        *reinterpret_cast<float4*>(&sW[idx]) =
            *reinterpret_cast<const float4*>(&W[idx]);
    }
}

__device__ __forceinline__ void mm_tile(float acc[4][4], const float* sA, const float* sW,
                                        int r0, int c0) {
#pragma unroll 8
    for (int k = 0; k < 64; k++) {
        float4 w = *reinterpret_cast<const float4*>(&sW[k * 64 + c0]);
        float a[4];
#pragma unroll
        for (int i = 0; i < 4; i++) a[i] = sA[(r0 + i) * APITCH + k];
#pragma unroll
        for (int i = 0; i < 4; i++) {
            acc[i][0] = fmaf(a[i], w.x, acc[i][0]);
            acc[i][1] = fmaf(a[i], w.y, acc[i][1]);
            acc[i][2] = fmaf(a[i], w.z, acc[i][2]);
            acc[i][3] = fmaf(a[i], w.w, acc[i][3]);
        }
    }
}

// ---------------------------------------------------------------------------
// k_input: state = relu(x @ in_W + in_b); msg(fp16) = relu(state @ msg_W[0] + b0)
// ---------------------------------------------------------------------------
__global__ __launch_bounds__(256) void k_input(const float* __restrict__ x,
                       const float* __restrict__ W,  const float* __restrict__ b,
                       const float* __restrict__ mW, const float* __restrict__ mb) {
    __shared__ float sA[TILE_ROWS * APITCH];
    __shared__ float sW[64 * 64];

    int tid = threadIdx.x;
    int ty = tid >> 4, tx = tid & 15;
    int r0 = ty * 4, c0 = tx * 4;
    int blkRow = blockIdx.x * TILE_ROWS;

    float acc[4][4];
#pragma unroll
    for (int i = 0; i < 4; i++)
#pragma unroll
        for (int j = 0; j < 4; j++) acc[i][j] = 0.0f;

#pragma unroll
    for (int chunk = 0; chunk < 2; chunk++) {
        load_tileA(sA, x, blkRow, FEAT, chunk * 64, tid);
        load_tileW(sW, W + chunk * 64 * STATE, tid);
        __syncthreads();
        mm_tile(acc, sA, sW, r0, c0);
        __syncthreads();
    }

    float4 bias = *reinterpret_cast<const float4*>(&b[c0]);
    float st[4][4];
#pragma unroll
    for (int i = 0; i < 4; i++) {
        st[i][0] = fmaxf(acc[i][0] + bias.x, 0.0f);
        st[i][1] = fmaxf(acc[i][1] + bias.y, 0.0f);
        st[i][2] = fmaxf(acc[i][2] + bias.z, 0.0f);
        st[i][3] = fmaxf(acc[i][3] + bias.w, 0.0f);
        int gr = blkRow + r0 + i;
        if (gr < N_NODES)
            *reinterpret_cast<float4*>(&g_state[gr * STATE + c0]) =
                make_float4(st[i][0], st[i][1], st[i][2], st[i][3]);
    }

    // msg[0] from the state tile (reuse smem)
#pragma unroll
    for (int i = 0; i < 4; i++)
        *reinterpret_cast<float4*>(&sA[(r0 + i) * APITCH + c0]) =
            make_float4(st[i][0], st[i][1], st[i][2], st[i][3]);
    load_tileW(sW, mW, tid);
    __syncthreads();

#pragma unroll
    for (int i = 0; i < 4; i++)
#pragma unroll
        for (int j = 0; j < 4; j++) acc[i][j] = 0.0f;
    mm_tile(acc, sA, sW, r0, c0);

    float4 mbias = *reinterpret_cast<const float4*>(&mb[c0]);
#pragma unroll
    for (int i = 0; i < 4; i++) {
        int gr = blkRow + r0 + i;
        if (gr < N_NODES)
            st_msg4(&g_msg[gr * STATE + c0],
                    fmaxf(acc[i][0] + mbias.x, 0.0f),
                    fmaxf(acc[i][1] + mbias.y, 0.0f),
                    fmaxf(acc[i][2] + mbias.z, 0.0f),
                    fmaxf(acc[i][3] + mbias.w, 0.0f));
    }
}

// ---------------------------------------------------------------------------
// CSR gather: agg[n] = sum_{e in csr(n)} msg[esrc[e]]   (atomic-free)
// 16 threads/node, 4-half (8B) lanes -> one 128B line per edge row.
// fp16 loads, fp32 accumulate.
// ---------------------------------------------------------------------------
__global__ __launch_bounds__(256) void k_gather() {
    int t = blockIdx.x * blockDim.x + threadIdx.x;
    int node = t >> 4;
    if (node >= N_NODES) return;
    int c = (t & 15) << 2;                     // half-offset (x4)

    int e   = __ldg(&g_rowptr[node]);
    int end = __ldg(&g_rowptr[node + 1]);

    float4 acc = make_float4(0.f, 0.f, 0.f, 0.f);
    for (; e + 3 < end; e += 4) {
        int s0 = __ldg(&g_esrc[e]);
        int s1 = __ldg(&g_esrc[e + 1]);
        int s2 = __ldg(&g_esrc[e + 2]);
        int s3 = __ldg(&g_esrc[e + 3]);
        float4 v0 = ld_msg4(&g_msg[s0 * STATE + c]);
        float4 v1 = ld_msg4(&g_msg[s1 * STATE + c]);
        float4 v2 = ld_msg4(&g_msg[s2 * STATE + c]);
        float4 v3 = ld_msg4(&g_msg[s3 * STATE + c]);
        acc.x += (v0.x + v1.x) + (v2.x + v3.x);
        acc.y += (v0.y + v1.y) + (v2.y + v3.y);
        acc.z += (v0.z + v1.z) + (v2.z + v3.z);
        acc.w += (v0.w + v1.w) + (v2.w + v3.w);
    }
    for (; e < end; e++) {
        int s0 = __ldg(&g_esrc[e]);
        float4 v0 = ld_msg4(&g_msg[s0 * STATE + c]);
        acc.x += v0.x; acc.y += v0.y; acc.z += v0.z; acc.w += v0.w;
    }
    *reinterpret_cast<float4*>(&g_agg[node * STATE + c]) = acc;
}

// ---------------------------------------------------------------------------
// k_upd: state += relu(agg @ upd_W[r] + upd_b[r])
//        if HAS_MSG: msg(fp16) = relu(state @ msg_W[r+1] + msg_b[r+1])
// Safe: launch boundary orders gather reads of msg before these writes.
// ---------------------------------------------------------------------------
template <int HAS_MSG>
__global__ __launch_bounds__(256) void k_upd(const float* __restrict__ W,  const float* __restrict__ b,
                     const float* __restrict__ mW, const float* __restrict__ mb) {
    __shared__ float sA[TILE_ROWS * APITCH];
    __shared__ float sW[64 * 64];

    int tid = threadIdx.x;
    int ty = tid >> 4, tx = tid & 15;
    int r0 = ty * 4, c0 = tx * 4;
    int blkRow = blockIdx.x * TILE_ROWS;

    load_tileA(sA, g_agg, blkRow, STATE, 0, tid);
    load_tileW(sW, W, tid);
    __syncthreads();

    float acc[4][4];
#pragma unroll
    for (int i = 0; i < 4; i++)
#pragma unroll
        for (int j = 0; j < 4; j++) acc[i][j] = 0.0f;
    mm_tile(acc, sA, sW, r0, c0);

    float4 bias = *reinterpret_cast<const float4*>(&b[c0]);
    float st[4][4];
#pragma unroll
    for (int i = 0; i < 4; i++) {
        int gr = blkRow + r0 + i;
        if (gr < N_NODES) {
            float4 old = *reinterpret_cast<const float4*>(&g_state[gr * STATE + c0]);
            st[i][0] = old.x + fmaxf(acc[i][0] + bias.x, 0.0f);
            st[i][1] = old.y + fmaxf(acc[i][1] + bias.y, 0.0f);
            st[i][2] = old.z + fmaxf(acc[i][2] + bias.z, 0.0f);
            st[i][3] = old.w + fmaxf(acc[i][3] + bias.w, 0.0f);
            *reinterpret_cast<float4*>(&g_state[gr * STATE + c0]) =
                make_float4(st[i][0], st[i][1], st[i][2], st[i][3]);
        } else {
            st[i][0] = st[i][1] = st[i][2] = st[i][3] = 0.0f;
        }
    }

    if (HAS_MSG) {
        __syncthreads();
#pragma unroll
        for (int i = 0; i < 4; i++)
            *reinterpret_cast<float4*>(&sA[(r0 + i) * APITCH + c0]) =
                make_float4(st[i][0], st[i][1], st[i][2], st[i][3]);
        load_tileW(sW, mW, tid);
        __syncthreads();

#pragma unroll
        for (int i = 0; i < 4; i++)
#pragma unroll
            for (int j = 0; j < 4; j++) acc[i][j] = 0.0f;
        mm_tile(acc, sA, sW, r0, c0);

        float4 mbias = *reinterpret_cast<const float4*>(&mb[c0]);
#pragma unroll
        for (int i = 0; i < 4; i++) {
            int gr = blkRow + r0 + i;
            if (gr < N_NODES)
                st_msg4(&g_msg[gr * STATE + c0],
                        fmaxf(acc[i][0] + mbias.x, 0.0f),
                        fmaxf(acc[i][1] + mbias.y, 0.0f),
                        fmaxf(acc[i][2] + mbias.z, 0.0f),
                        fmaxf(acc[i][3] + mbias.w, 0.0f));
        }
    }
}

// ---------------------------------------------------------------------------
// graph_state = segment_sum(state, batch)  -> [256, 64]
// ---------------------------------------------------------------------------
__global__ void k_pool(const int* __restrict__ batch) {
    int t = blockIdx.x * blockDim.x + threadIdx.x;
    int row = t >> 4;
    if (row >= N_NODES) return;
    int c = (t & 15) << 2;
    int g = __ldg(&batch[row]);

    const float4 v = *reinterpret_cast<const float4*>(&g_state[row * STATE + c]);
    float* a = &g_graph[g * STATE + c];
    asm volatile("red.global.add.v4.f32 [%0], {%1,%2,%3,%4};"
                 :: "l"(a), "f"(v.x), "f"(v.y), "f"(v.z), "f"(v.w)
                 : "memory");
}

// ---------------------------------------------------------------------------
// mean = gs @ mean_W + mean_b ; std = exp(0.5*clip(gs @ lv_W + lv_b, -20, 2))
// ---------------------------------------------------------------------------
__global__ void k_head(const float* __restrict__ meanW, const float* __restrict__ meanB,
                       const float* __restrict__ lvW,   const float* __restrict__ lvB,
                       float* __restrict__ out) {
    __shared__ float s[STATE];
    int g = blockIdx.x;
    int m = threadIdx.x;
    s[m]      = g_graph[g * STATE + m];
    s[m + 32] = g_graph[g * STATE + m + 32];
    __syncthreads();

    float accM = meanB[m];
    float accL = lvB[m];
#pragma unroll
    for (int k = 0; k < STATE; k++) {
        float sv = s[k];
        accM = fmaf(sv, meanW[k * M_OUT + m], accM);
        accL = fmaf(sv, lvW[k * M_OUT + m], accL);
    }
    out[g * M_OUT + m] = accM;
    float lv = fminf(fmaxf(accL, -20.0f), 2.0f);
    out[N_GRAPHS * M_OUT + g * M_OUT + m] = expf(0.5f * lv);
}

// ---------------------------------------------------------------------------
extern "C" void kernel_launch(void* const* d_in, const int* in_sizes, int n_in,
                              void* d_out, int out_size) {
    const float* x     = (const float*)d_in[0];
    const int*   ei    = (const int*)d_in[1];
    const int*   batch = (const int*)d_in[2];
    const float* in_W  = (const float*)d_in[3];
    const float* in_b  = (const float*)d_in[4];
    const float* msg_W = (const float*)d_in[5];    // [4,64,64]
    const float* msg_b = (const float*)d_in[6];    // [4,64]
    const float* upd_W = (const float*)d_in[7];
    const float* upd_b = (const float*)d_in[8];
    const float* meanW = (const float*)d_in[9];
    const float* meanB = (const float*)d_in[10];
    const float* lvW   = (const float*)d_in[11];
    const float* lvB   = (const float*)d_in[12];
    float* out = (float*)d_out;

    const int zeroBlocks   = (N_NODES + 255) / 256;
    const int edgeBlocks   = (N_EDGES + 255) / 256;
    const int gatherBlocks = (N_NODES * 16 + 255) / 256;
    const int poolBlocks   = (N_NODES * 16 + 255) / 256;

    // CSR build (once per launch; reused by all 4 rounds)
    k_zero<<<zeroBlocks, 256>>>();
    k_hist<<<edgeBlocks, 256>>>(ei);
    k_scan<<<1, 1024>>>();
    k_scatter<<<edgeBlocks, 256>>>(ei);

    k_input<<<ROW_BLOCKS, 256>>>(x, in_W, in_b, msg_W, msg_b);  // state + msg[0]

    for (int r = 0; r < ROUNDS; r++) {
        k_gather<<<gatherBlocks, 256>>>();
        const float* uW = upd_W + r * STATE * STATE;
        const float* ub = upd_b + r * STATE;
        if (r < ROUNDS - 1) {
            k_upd<1><<<ROW_BLOCKS, 256>>>(uW, ub,
                                          msg_W + (r + 1) * STATE * STATE,
                                          msg_b + (r + 1) * STATE);
        } else {
            k_upd<0><<<ROW_BLOCKS, 256>>>(uW, ub, nullptr, nullptr);
        }
    }

    k_pool<<<poolBlocks, 256>>>(batch);
    k_head<<<N_GRAPHS, M_OUT>>>(meanW, meanB, lvW, lvB, out);
}

// round 14
// speedup vs baseline: 1.3486x; 1.2882x over previous
#include <cuda_runtime.h>
#include <cuda_fp16.h>
#include <mma.h>
#include <math.h>

using namespace nvcuda;

#define N_NODES  50000
#define N_EDGES  800000
#define N_GRAPHS 256
#define FEAT     128
#define STATE    64
#define ROUNDS   4
#define M_OUT    32

#define TILE_ROWS 64
#define HPITCH    72          // half pitch (multiple of 8, conflict-skewed)
#define CPITCH    68          // float pitch for fp32 result tile
#define ROW_BLOCKS ((N_NODES + TILE_ROWS - 1) / TILE_ROWS)   // 782

// Scratch (allocation-free rule: __device__ globals)
__device__ float  g_state[N_NODES * STATE];   // 12.8 MB
__device__ __half g_msg[N_NODES * STATE];     // 6.4 MB (fp16 message buffer)
__device__ float  g_agg[N_NODES * STATE];     // 12.8 MB
__device__ float  g_graph[N_GRAPHS * STATE];  // 64 KB
// CSR-by-dst scratch (built once per launch, reused all 4 rounds)
__device__ int    g_cnt[N_NODES];
__device__ int    g_rowptr[N_NODES + 1];
__device__ int    g_cursor[N_NODES];
__device__ int    g_esrc[N_EDGES];

// ---------------------------------------------------------------------------
__global__ void k_zero() {
    int t = blockIdx.x * blockDim.x + threadIdx.x;
    if (t < N_NODES) g_cnt[t] = 0;
    if (t < N_GRAPHS * STATE) g_graph[t] = 0.0f;
}

// ---------------------------------------------------------------------------
// CSR build: histogram of dst, scan, scatter of src ids
// ---------------------------------------------------------------------------
__global__ void k_hist(const int* __restrict__ ei) {
    int t = blockIdx.x * blockDim.x + threadIdx.x;
    if (t < N_EDGES) atomicAdd(&g_cnt[__ldg(&ei[N_EDGES + t])], 1);
}

__global__ __launch_bounds__(1024) void k_scan() {
    __shared__ int ps[1024];
    const int CH = (N_NODES + 1023) / 1024;   // 49
    int t = threadIdx.x;
    int base = t * CH;

    int sum = 0;
    for (int i = 0; i < CH; i++) {
        int idx = base + i;
        if (idx < N_NODES) sum += g_cnt[idx];
    }
    ps[t] = sum;
    __syncthreads();
    for (int off = 1; off < 1024; off <<= 1) {
        int v = (t >= off) ? ps[t - off] : 0;
        __syncthreads();
        ps[t] += v;
        __syncthreads();
    }
    int run = (t == 0) ? 0 : ps[t - 1];
    for (int i = 0; i < CH; i++) {
        int idx = base + i;
        if (idx < N_NODES) {
            int c = g_cnt[idx];
            g_rowptr[idx] = run;
            g_cursor[idx] = run;
            run += c;
        }
    }
    if (t == 1023) g_rowptr[N_NODES] = run;   // = N_EDGES
}

__global__ void k_scatter(const int* __restrict__ ei) {
    int t = blockIdx.x * blockDim.x + threadIdx.x;
    if (t >= N_EDGES) return;
    int d = __ldg(&ei[N_EDGES + t]);
    int pos = atomicAdd(&g_cursor[d], 1);
    g_esrc[pos] = __ldg(&ei[t]);
}

// ===========================================================================
// fp16 helpers
// ===========================================================================
__device__ __forceinline__ float4 ld_msg4(const __half* p) {   // 4 halves (8B)
    uint2 u = *reinterpret_cast<const uint2*>(p);
    float2 f0 = __half22float2(*reinterpret_cast<__half2*>(&u.x));
    float2 f1 = __half22float2(*reinterpret_cast<__half2*>(&u.y));
    return make_float4(f0.x, f0.y, f1.x, f1.y);
}

__device__ __forceinline__ void st_half4(__half* p, float a, float b, float c, float d) {
    uint2 u;
    *reinterpret_cast<__half2*>(&u.x) = __floats2half2_rn(a, b);
    *reinterpret_cast<__half2*>(&u.y) = __floats2half2_rn(c, d);
    *reinterpret_cast<uint2*>(p) = u;
}

// ===========================================================================
// wmma GEMM building blocks (64x64 tile, fp16 in, fp32 acc)
// ===========================================================================

// fp32 global (row-major, stride) -> fp16 smem tile [64][HPITCH]
__device__ __forceinline__ void load_tileA_h(__half* sAh, const float* __restrict__ src,
                                             int blkRow, int rowStride, int colOff, int tid) {
#pragma unroll
    for (int p = 0; p < 4; p++) {
        int idx = p * 1024 + tid * 4;
        int row = idx >> 6, col = idx & 63;
        float4 v = make_float4(0.f, 0.f, 0.f, 0.f);
        int gr = blkRow + row;
        if (gr < N_NODES)
            v = *reinterpret_cast<const float4*>(&src[gr * rowStride + colOff + col]);
        st_half4(&sAh[row * HPITCH + col], v.x, v.y, v.z, v.w);
    }
}

// fp32 weights (contiguous 64x64) -> fp16 smem [64][HPITCH]
__device__ __forceinline__ void load_tileW_h(__half* sBh, const float* __restrict__ W, int tid) {
#pragma unroll
    for (int p = 0; p < 4; p++) {
        int idx = p * 1024 + tid * 4;
        int row = idx >> 6, col = idx & 63;
        float4 v = *reinterpret_cast<const float4*>(&W[idx]);
        st_half4(&sBh[row * HPITCH + col], v.x, v.y, v.z, v.w);
    }
}

// C[64][CPITCH] (+)= A[64][64] @ B[64][64], via 8 warps x 2 tiles of 16x16.
// ACCUM=0: overwrite sC; ACCUM=1: add into existing sC.
template <int ACCUM>
__device__ __forceinline__ void wmma_64x64(float* sC, const __half* sAh, const __half* sBh,
                                           int warp) {
#pragma unroll
    for (int t = 0; t < 2; t++) {
        int tile = warp * 2 + t;
        int tr = tile >> 2, tc = tile & 3;
        wmma::fragment<wmma::accumulator, 16, 16, 16, float> c;
        if (ACCUM)
            wmma::load_matrix_sync(c, sC + tr * 16 * CPITCH + tc * 16, CPITCH,
                                   wmma::mem_row_major);
        else
            wmma::fill_fragment(c, 0.0f);
#pragma unroll
        for (int kk = 0; kk < 4; kk++) {
            wmma::fragment<wmma::matrix_a, 16, 16, 16, __half, wmma::row_major> a;
            wmma::fragment<wmma::matrix_b, 16, 16, 16, __half, wmma::row_major> b;
            wmma::load_matrix_sync(a, sAh + tr * 16 * HPITCH + kk * 16, HPITCH);
            wmma::load_matrix_sync(b, sBh + kk * 16 * HPITCH + tc * 16, HPITCH);
            wmma::mma_sync(c, a, b, c);
        }
        wmma::store_matrix_sync(sC + tr * 16 * CPITCH + tc * 16, c, CPITCH,
                                wmma::mem_row_major);
    }
}

// ---------------------------------------------------------------------------
// k_input: state = relu(x @ in_W + in_b); msg(fp16) = relu(state @ msg_W[0] + b0)
// ---------------------------------------------------------------------------
__global__ __launch_bounds__(256) void k_input(const float* __restrict__ x,
                       const float* __restrict__ W,  const float* __restrict__ b,
                       const float* __restrict__ mW, const float* __restrict__ mb) {
    __shared__ __half sAh[TILE_ROWS * HPITCH];
    __shared__ __half sBh[64 * HPITCH];
    __shared__ float  sC[TILE_ROWS * CPITCH];

    int tid = threadIdx.x;
    int warp = tid >> 5;
    int ty = tid >> 4, tx = tid & 15;
    int r0 = ty * 4, c0 = tx * 4;
    int blkRow = blockIdx.x * TILE_ROWS;

    // K=128 in two 64-chunks, accumulating in sC
#pragma unroll
    for (int chunk = 0; chunk < 2; chunk++) {
        load_tileA_h(sAh, x, blkRow, FEAT, chunk * 64, tid);
        load_tileW_h(sBh, W + chunk * 64 * STATE, tid);
        __syncthreads();
        if (chunk == 0) wmma_64x64<0>(sC, sAh, sBh, warp);
        else            wmma_64x64<1>(sC, sAh, sBh, warp);
        __syncthreads();
    }

    float4 bias = *reinterpret_cast<const float4*>(&b[c0]);
    float st[4][4];
#pragma unroll
    for (int i = 0; i < 4; i++) {
        float4 v = *reinterpret_cast<const float4*>(&sC[(r0 + i) * CPITCH + c0]);
        st[i][0] = fmaxf(v.x + bias.x, 0.0f);
        st[i][1] = fmaxf(v.y + bias.y, 0.0f);
        st[i][2] = fmaxf(v.z + bias.z, 0.0f);
        st[i][3] = fmaxf(v.w + bias.w, 0.0f);
        int gr = blkRow + r0 + i;
        if (gr < N_NODES)
            *reinterpret_cast<float4*>(&g_state[gr * STATE + c0]) =
                make_float4(st[i][0], st[i][1], st[i][2], st[i][3]);
    }
    __syncthreads();   // done reading sC / sAh

    // msg[0] = relu(state @ msg_W[0] + mb): state tile -> fp16 sAh
#pragma unroll
    for (int i = 0; i < 4; i++)
        st_half4(&sAh[(r0 + i) * HPITCH + c0], st[i][0], st[i][1], st[i][2], st[i][3]);
    load_tileW_h(sBh, mW, tid);
    __syncthreads();

    wmma_64x64<0>(sC, sAh, sBh, warp);
    __syncthreads();

    float4 mbias = *reinterpret_cast<const float4*>(&mb[c0]);
#pragma unroll
    for (int i = 0; i < 4; i++) {
        int gr = blkRow + r0 + i;
        if (gr < N_NODES) {
            float4 v = *reinterpret_cast<const float4*>(&sC[(r0 + i) * CPITCH + c0]);
            st_half4(&g_msg[gr * STATE + c0],
                     fmaxf(v.x + mbias.x, 0.0f),
                     fmaxf(v.y + mbias.y, 0.0f),
                     fmaxf(v.z + mbias.z, 0.0f),
                     fmaxf(v.w + mbias.w, 0.0f));
        }
    }
}

// ---------------------------------------------------------------------------
// CSR gather: agg[n] = sum_{e in csr(n)} msg[esrc[e]]   (atomic-free)
// 16 threads/node, 4-half (8B) lanes. fp16 loads, fp32 accumulate.
// ---------------------------------------------------------------------------
__global__ __launch_bounds__(256) void k_gather() {
    int t = blockIdx.x * blockDim.x + threadIdx.x;
    int node = t >> 4;
    if (node >= N_NODES) return;
    int c = (t & 15) << 2;                     // half-offset (x4)

    int e   = __ldg(&g_rowptr[node]);
    int end = __ldg(&g_rowptr[node + 1]);

    float4 acc = make_float4(0.f, 0.f, 0.f, 0.f);
    for (; e + 3 < end; e += 4) {
        int s0 = __ldg(&g_esrc[e]);
        int s1 = __ldg(&g_esrc[e + 1]);
        int s2 = __ldg(&g_esrc[e + 2]);
        int s3 = __ldg(&g_esrc[e + 3]);
        float4 v0 = ld_msg4(&g_msg[s0 * STATE + c]);
        float4 v1 = ld_msg4(&g_msg[s1 * STATE + c]);
        float4 v2 = ld_msg4(&g_msg[s2 * STATE + c]);
        float4 v3 = ld_msg4(&g_msg[s3 * STATE + c]);
        acc.x += (v0.x + v1.x) + (v2.x + v3.x);
        acc.y += (v0.y + v1.y) + (v2.y + v3.y);
        acc.z += (v0.z + v1.z) + (v2.z + v3.z);
        acc.w += (v0.w + v1.w) + (v2.w + v3.w);
    }
    for (; e < end; e++) {
        int s0 = __ldg(&g_esrc[e]);
        float4 v0 = ld_msg4(&g_msg[s0 * STATE + c]);
        acc.x += v0.x; acc.y += v0.y; acc.z += v0.z; acc.w += v0.w;
    }
    *reinterpret_cast<float4*>(&g_agg[node * STATE + c]) = acc;
}

// ---------------------------------------------------------------------------
// k_upd: state += relu(agg @ upd_W[r] + upd_b[r])
//        if HAS_MSG: msg(fp16) = relu(state @ msg_W[r+1] + msg_b[r+1])
// Tensor-core (HMMA fp16) version.
// ---------------------------------------------------------------------------
template <int HAS_MSG>
__global__ __launch_bounds__(256) void k_upd(const float* __restrict__ W,  const float* __restrict__ b,
                     const float* __restrict__ mW, const float* __restrict__ mb) {
    __shared__ __half sAh[TILE_ROWS * HPITCH];
    __shared__ __half sBh[64 * HPITCH];
    __shared__ float  sC[TILE_ROWS * CPITCH];

    int tid = threadIdx.x;
    int warp = tid >> 5;
    int ty = tid >> 4, tx = tid & 15;
    int r0 = ty * 4, c0 = tx * 4;
    int blkRow = blockIdx.x * TILE_ROWS;

    load_tileA_h(sAh, g_agg, blkRow, STATE, 0, tid);
    load_tileW_h(sBh, W, tid);
    __syncthreads();

    wmma_64x64<0>(sC, sAh, sBh, warp);
    __syncthreads();

    float4 bias = *reinterpret_cast<const float4*>(&b[c0]);
    float st[4][4];
#pragma unroll
    for (int i = 0; i < 4; i++) {
        int gr = blkRow + r0 + i;
        if (gr < N_NODES) {
            float4 v   = *reinterpret_cast<const float4*>(&sC[(r0 + i) * CPITCH + c0]);
            float4 old = *reinterpret_cast<const float4*>(&g_state[gr * STATE + c0]);
            st[i][0] = old.x + fmaxf(v.x + bias.x, 0.0f);
            st[i][1] = old.y + fmaxf(v.y + bias.y, 0.0f);
            st[i][2] = old.z + fmaxf(v.z + bias.z, 0.0f);
            st[i][3] = old.w + fmaxf(v.w + bias.w, 0.0f);
            *reinterpret_cast<float4*>(&g_state[gr * STATE + c0]) =
                make_float4(st[i][0], st[i][1], st[i][2], st[i][3]);
        } else {
            st[i][0] = st[i][1] = st[i][2] = st[i][3] = 0.0f;
        }
    }

    if (HAS_MSG) {
        __syncthreads();
#pragma unroll
        for (int i = 0; i < 4; i++)
            st_half4(&sAh[(r0 + i) * HPITCH + c0], st[i][0], st[i][1], st[i][2], st[i][3]);
        load_tileW_h(sBh, mW, tid);
        __syncthreads();

        wmma_64x64<0>(sC, sAh, sBh, warp);
        __syncthreads();

        float4 mbias = *reinterpret_cast<const float4*>(&mb[c0]);
#pragma unroll
        for (int i = 0; i < 4; i++) {
            int gr = blkRow + r0 + i;
            if (gr < N_NODES) {
                float4 v = *reinterpret_cast<const float4*>(&sC[(r0 + i) * CPITCH + c0]);
                st_half4(&g_msg[gr * STATE + c0],
                         fmaxf(v.x + mbias.x, 0.0f),
                         fmaxf(v.y + mbias.y, 0.0f),
                         fmaxf(v.z + mbias.z, 0.0f),
                         fmaxf(v.w + mbias.w, 0.0f));
            }
        }
    }
}

// ---------------------------------------------------------------------------
// graph_state = segment_sum(state, batch)  -> [256, 64]
// ---------------------------------------------------------------------------
__global__ void k_pool(const int* __restrict__ batch) {
    int t = blockIdx.x * blockDim.x + threadIdx.x;
    int row = t >> 4;
    if (row >= N_NODES) return;
    int c = (t & 15) << 2;
    int g = __ldg(&batch[row]);

    const float4 v = *reinterpret_cast<const float4*>(&g_state[row * STATE + c]);
    float* a = &g_graph[g * STATE + c];
    asm volatile("red.global.add.v4.f32 [%0], {%1,%2,%3,%4};"
                 :: "l"(a), "f"(v.x), "f"(v.y), "f"(v.z), "f"(v.w)
                 : "memory");
}

// ---------------------------------------------------------------------------
// mean = gs @ mean_W + mean_b ; std = exp(0.5*clip(gs @ lv_W + lv_b, -20, 2))
// ---------------------------------------------------------------------------
__global__ void k_head(const float* __restrict__ meanW, const float* __restrict__ meanB,
                       const float* __restrict__ lvW,   const float* __restrict__ lvB,
                       float* __restrict__ out) {
    __shared__ float s[STATE];
    int g = blockIdx.x;
    int m = threadIdx.x;
    s[m]      = g_graph[g * STATE + m];
    s[m + 32] = g_graph[g * STATE + m + 32];
    __syncthreads();

    float accM = meanB[m];
    float accL = lvB[m];
#pragma unroll
    for (int k = 0; k < STATE; k++) {
        float sv = s[k];
        accM = fmaf(sv, meanW[k * M_OUT + m], accM);
        accL = fmaf(sv, lvW[k * M_OUT + m], accL);
    }
    out[g * M_OUT + m] = accM;
    float lv = fminf(fmaxf(accL, -20.0f), 2.0f);
    out[N_GRAPHS * M_OUT + g * M_OUT + m] = expf(0.5f * lv);
}

// ---------------------------------------------------------------------------
extern "C" void kernel_launch(void* const* d_in, const int* in_sizes, int n_in,
                              void* d_out, int out_size) {
    const float* x     = (const float*)d_in[0];
    const int*   ei    = (const int*)d_in[1];
    const int*   batch = (const int*)d_in[2];
    const float* in_W  = (const float*)d_in[3];
    const float* in_b  = (const float*)d_in[4];
    const float* msg_W = (const float*)d_in[5];    // [4,64,64]
    const float* msg_b = (const float*)d_in[6];    // [4,64]
    const float* upd_W = (const float*)d_in[7];
    const float* upd_b = (const float*)d_in[8];
    const float* meanW = (const float*)d_in[9];
    const float* meanB = (const float*)d_in[10];
    const float* lvW   = (const float*)d_in[11];
    const float* lvB   = (const float*)d_in[12];
    float* out = (float*)d_out;

    const int zeroBlocks   = (N_NODES + 255) / 256;
    const int edgeBlocks   = (N_EDGES + 255) / 256;
    const int gatherBlocks = (N_NODES * 16 + 255) / 256;
    const int poolBlocks   = (N_NODES * 16 + 255) / 256;

    // CSR build (once per launch; reused by all 4 rounds)
    k_zero<<<zeroBlocks, 256>>>();
    k_hist<<<edgeBlocks, 256>>>(ei);
    k_scan<<<1, 1024>>>();
    k_scatter<<<edgeBlocks, 256>>>(ei);

    k_input<<<ROW_BLOCKS, 256>>>(x, in_W, in_b, msg_W, msg_b);  // state + msg[0]

    for (int r = 0; r < ROUNDS; r++) {
        k_gather<<<gatherBlocks, 256>>>();
        const float* uW = upd_W + r * STATE * STATE;
        const float* ub = upd_b + r * STATE;
        if (r < ROUNDS - 1) {
            k_upd<1><<<ROW_BLOCKS, 256>>>(uW, ub,
                                          msg_W + (r + 1) * STATE * STATE,
                                          msg_b + (r + 1) * STATE);
        } else {
            k_upd<0><<<ROW_BLOCKS, 256>>>(uW, ub, nullptr, nullptr);
        }
    }

    k_pool<<<poolBlocks, 256>>>(batch);
    k_head<<<N_GRAPHS, M_OUT>>>(meanW, meanB, lvW, lvB, out);
}